// round 7
// baseline (speedup 1.0000x reference)
#include <cuda_runtime.h>
#include <cuda_bf16.h>
#include <math.h>

// Problem constants (match reference)
#define NBX     512
#define NBY     512
#define BSX     1.953125f   // 1000/512, exact in fp32
#define BSY     1.953125f
#define INV_BS  0.512f      // rn(1/BSX); product path, exact-div fallback near bins
#define INV_UPC 10.0f       // 1 / UNIT_PIN_CAP

// Quad map scratch: Q[bx][by] = {u[bx][by], u[bx][by1], u[bx1][by], u[bx1][by1]}
// with bx1 = min(bx+1, 511), by1 = min(by+1, 511). 4 MB static device array.
__device__ float4 g_quad[NBX * NBY];

__global__ __launch_bounds__(256) void build_quad_kernel(
    const float* __restrict__ umap)
{
    int idx = blockIdx.x * blockDim.x + threadIdx.x;
    if (idx >= NBX * NBY) return;
    int bx = idx >> 9;
    int by = idx & (NBY - 1);
    int bx1 = min(bx + 1, NBX - 1);
    int by1 = min(by + 1, NBY - 1);
    const float* r0 = umap + bx  * NBY;
    const float* r1 = umap + bx1 * NBY;
    float4 q;
    q.x = __ldg(&r0[by]);
    q.y = __ldg(&r0[by1]);
    q.z = __ldg(&r1[by]);
    q.w = __ldg(&r1[by1]);
    g_quad[idx] = q;
}

// Compute clipped quad index for one node (with rare exact-div fallback),
// and the four axis overlaps.
__device__ __forceinline__ int node_bins(
    float x, float y, float w, float h,
    float& ox0, float& ox1, float& oy0, float& oy1)
{
    // Fast bin quotients via multiply; error < 2.5e-7 relative.
    float qx = x * INV_BS;
    float qy = y * INV_BS;

    // If either quotient is within a few ulp of an integer, the fast floor
    // could disagree with the reference's floor(div.rn). Redo exactly.
    float dx = fabsf(qx - rintf(qx));
    float dy = fabsf(qy - rintf(qy));
    float tx = fmaxf(qx, 1.0f) * 5e-7f;
    float ty = fmaxf(qy, 1.0f) * 5e-7f;
    if (dx < tx || dy < ty) {            // rare (~1e-4 of nodes)
        qx = x / BSX;
        qy = y / BSY;
    }

    float fbx = floorf(qx);
    float fby = floorf(qy);

    float hix = x + w;
    float hiy = y + h;

    // Overlaps use UNCLIPPED bin positions (as in reference).
    float blx0 = fbx * BSX;
    ox0 = fmaxf(fminf(hix, blx0 + BSX)        - fmaxf(x, blx0),       0.0f);
    ox1 = fmaxf(fminf(hix, blx0 + 2.0f * BSX) - fmaxf(x, blx0 + BSX), 0.0f);

    float bly0 = fby * BSY;
    oy0 = fmaxf(fminf(hiy, bly0 + BSY)        - fmaxf(y, bly0),       0.0f);
    oy1 = fmaxf(fminf(hiy, bly0 + 2.0f * BSY) - fmaxf(y, bly0 + BSY), 0.0f);

    int bx0c = min(max((int)fbx, 0), NBX - 1);
    int by0c = min(max((int)fby, 0), NBY - 1);
    return (bx0c << 9) | by0c;
}

// 4 nodes per thread: deep ILP (4 independent gather chains) at >=48 warps/SM.
__global__ __launch_bounds__(256, 6) void node_area_kernel_v9(
    const float* __restrict__ pos,        // [2N]: x then y
    const float* __restrict__ nsx,        // [N]
    const float* __restrict__ nsy,        // [N]
    const int*   __restrict__ pw,         // [N]
    float*       __restrict__ out,        // [N]
    int n)
{
    int base = (blockIdx.x * blockDim.x + threadIdx.x) * 4;
    if (base >= n) return;
    // N is a multiple of 4, so full float4 accesses are always valid.

    float4 x4 = *(const float4*)(pos + base);
    float4 y4 = *(const float4*)(pos + n + base);
    float4 w4 = *(const float4*)(nsx + base);
    float4 h4 = *(const float4*)(nsy + base);
    int4   p4 = *(const int4*)(pw + base);

    float xs[4] = {x4.x, x4.y, x4.z, x4.w};
    float ys[4] = {y4.x, y4.y, y4.z, y4.w};
    float ws[4] = {w4.x, w4.y, w4.z, w4.w};
    float hs[4] = {h4.x, h4.y, h4.z, h4.w};
    int   ps[4] = {p4.x, p4.y, p4.z, p4.w};

    float ox0[4], ox1[4], oy0[4], oy1[4];
    float4 u[4];

    // Phase 1: bins + issue all 4 independent gathers
    #pragma unroll
    for (int k = 0; k < 4; k++) {
        int qidx = node_bins(xs[k], ys[k], ws[k], hs[k],
                             ox0[k], ox1[k], oy0[k], oy1[k]);
        u[k] = __ldg(&g_quad[qidx]);
    }

    // Phase 2: reduce + store
    float res[4];
    #pragma unroll
    for (int k = 0; k < 4; k++) {
        float area = ox0[k] * (oy0[k] * u[k].x + oy1[k] * u[k].y)
                   + ox1[k] * (oy0[k] * u[k].z + oy1[k] * u[k].w);
        res[k] = __fdividef(area * (float)ps[k] * INV_UPC, ws[k] * hs[k]);
    }

    float4 r;
    r.x = res[0]; r.y = res[1]; r.z = res[2]; r.w = res[3];
    *(float4*)(out + base) = r;
}

extern "C" void kernel_launch(void* const* d_in, const int* in_sizes, int n_in,
                              void* d_out, int out_size)
{
    const float* pos  = (const float*)d_in[0];
    const float* nsx  = (const float*)d_in[1];
    const float* nsy  = (const float*)d_in[2];
    const float* umap = (const float*)d_in[3];
    const int*   pw   = (const int*)d_in[4];
    float*       out  = (float*)d_out;

    int n = in_sizes[1];  // node_size_x has N elements

    // Pass 1: build the quad map (clip-at-edge baked in)
    {
        int total = NBX * NBY;
        int threads = 256;
        int blocks = (total + threads - 1) / threads;
        build_quad_kernel<<<blocks, threads>>>(umap);
    }

    // Pass 2: per-node area with a single float4 gather each
    {
        int threads = 256;
        int elems_per_block = threads * 4;
        int blocks = (n + elems_per_block - 1) / elems_per_block;
        node_area_kernel_v9<<<blocks, threads>>>(pos, nsx, nsy, pw, out, n);
    }
}

// round 8
// speedup vs baseline: 1.1822x; 1.1822x over previous
#include <cuda_runtime.h>
#include <cuda_bf16.h>
#include <math.h>

// Problem constants (match reference)
#define NBX     512
#define NBY     512
#define BSX     1.953125f   // 1000/512, exact in fp32
#define BSY     1.953125f
#define INV_BS  0.512f      // rn(1/BSX); product path, exact-div fallback near bins
#define INV_UPC 10.0f       // 1 / UNIT_PIN_CAP

// Quad map scratch: Q[bx][by] = {u[bx][by], u[bx][by1], u[bx1][by], u[bx1][by1]}
// with bx1 = min(bx+1, 511), by1 = min(by+1, 511). 4 MB static device array.
__device__ float4 g_quad[NBX * NBY];

__global__ __launch_bounds__(256) void build_quad_kernel(
    const float* __restrict__ umap)
{
    int idx = blockIdx.x * blockDim.x + threadIdx.x;
    if (idx >= NBX * NBY) return;
    int bx = idx >> 9;
    int by = idx & (NBY - 1);
    int bx1 = min(bx + 1, NBX - 1);
    int by1 = min(by + 1, NBY - 1);
    const float* r0 = umap + bx  * NBY;
    const float* r1 = umap + bx1 * NBY;
    float4 q;
    q.x = __ldg(&r0[by]);
    q.y = __ldg(&r0[by1]);
    q.z = __ldg(&r1[by]);
    q.w = __ldg(&r1[by1]);
    g_quad[idx] = q;
}

__device__ __forceinline__ float node_area(
    float x, float y, float w, float h, float ps)
{
    // Fast bin quotients via multiply; error < 2.5e-7 relative.
    float qx = x * INV_BS;
    float qy = y * INV_BS;

    // If either quotient is within a few ulp of an integer, the fast floor
    // could disagree with the reference's floor(div.rn). Redo exactly.
    float dx = fabsf(qx - rintf(qx));
    float dy = fabsf(qy - rintf(qy));
    float tx = fmaxf(qx, 1.0f) * 5e-7f;
    float ty = fmaxf(qy, 1.0f) * 5e-7f;
    if (dx < tx || dy < ty) {            // rare (~1e-4 of nodes)
        qx = x / BSX;
        qy = y / BSY;
    }

    float fbx = floorf(qx);
    float fby = floorf(qy);

    float hix = x + w;
    float hiy = y + h;

    // Overlaps use UNCLIPPED bin positions (as in reference).
    float blx0 = fbx * BSX;
    float ox0 = fmaxf(fminf(hix, blx0 + BSX)        - fmaxf(x, blx0),       0.0f);
    float ox1 = fmaxf(fminf(hix, blx0 + 2.0f * BSX) - fmaxf(x, blx0 + BSX), 0.0f);

    float bly0 = fby * BSY;
    float oy0 = fmaxf(fminf(hiy, bly0 + BSY)        - fmaxf(y, bly0),       0.0f);
    float oy1 = fmaxf(fminf(hiy, bly0 + 2.0f * BSY) - fmaxf(y, bly0 + BSY), 0.0f);

    // Clipped base indices; +1 clip is baked into the quad map.
    int bx0c = min(max((int)fbx, 0), NBX - 1);
    int by0c = min(max((int)fby, 0), NBY - 1);

    float4 u = __ldg(&g_quad[(bx0c << 9) | by0c]);

    float area = ox0 * (oy0 * u.x + oy1 * u.y)
               + ox1 * (oy0 * u.z + oy1 * u.w);

    return __fdividef(area * ps, w * h);
}

// Grid-stride with register double-buffering: next iteration's streaming
// loads are issued before processing the current one, removing the DRAM
// round-trip from the per-iteration critical path.
__global__ __launch_bounds__(256, 6) void node_area_kernel_v10(
    const float* __restrict__ pos,        // [2N]: x then y
    const float* __restrict__ nsx,        // [N]
    const float* __restrict__ nsy,        // [N]
    const int*   __restrict__ pw,         // [N]
    float*       __restrict__ out,        // [N]
    int n)
{
    int i = (blockIdx.x * blockDim.x + threadIdx.x) * 2;
    int stride = gridDim.x * blockDim.x * 2;

    if (i >= n) return;

    // Preload iteration 0 (N is even; full float2 accesses valid)
    float2 x2 = *(const float2*)(pos + i);
    float2 y2 = *(const float2*)(pos + n + i);
    float2 w2 = *(const float2*)(nsx + i);
    float2 h2 = *(const float2*)(nsy + i);
    int2   p2 = *(const int2*)(pw + i);

    while (true) {
        int inext = i + stride;
        bool more = inext < n;

        // Prefetch next iteration (independent loads, land while we compute)
        float2 nx, ny, nw, nh; int2 np;
        if (more) {
            nx = *(const float2*)(pos + inext);
            ny = *(const float2*)(pos + n + inext);
            nw = *(const float2*)(nsx + inext);
            nh = *(const float2*)(nsy + inext);
            np = *(const int2*)(pw + inext);
        }

        // Process current iteration
        float2 r;
        r.x = node_area(x2.x, y2.x, w2.x, h2.x, (float)p2.x * INV_UPC);
        r.y = node_area(x2.y, y2.y, w2.y, h2.y, (float)p2.y * INV_UPC);
        *(float2*)(out + i) = r;

        if (!more) break;
        x2 = nx; y2 = ny; w2 = nw; h2 = nh; p2 = np;
        i = inext;
    }
}

extern "C" void kernel_launch(void* const* d_in, const int* in_sizes, int n_in,
                              void* d_out, int out_size)
{
    const float* pos  = (const float*)d_in[0];
    const float* nsx  = (const float*)d_in[1];
    const float* nsy  = (const float*)d_in[2];
    const float* umap = (const float*)d_in[3];
    const int*   pw   = (const int*)d_in[4];
    float*       out  = (float*)d_out;

    int n = in_sizes[1];  // node_size_x has N elements

    // Pass 1: build the quad map (clip-at-edge baked in)
    {
        int total = NBX * NBY;
        int threads = 256;
        int blocks = (total + threads - 1) / threads;
        build_quad_kernel<<<blocks, threads>>>(umap);
    }

    // Pass 2: grid-stride, register double-buffered
    {
        int threads = 256;
        int blocks = 148 * 6;   // 6 resident blocks/SM target
        node_area_kernel_v10<<<blocks, threads>>>(pos, nsx, nsy, pw, out, n);
    }
}